// round 6
// baseline (speedup 1.0000x reference)
#include <cuda_runtime.h>

#define S_LEN 4096
#define HID 2048
#define NLAYERS 4

// ---------------- scan (recurrence) config ----------------
#define GBLK 128          // persistent blocks; all co-resident (proven)
#define ROWS_PER_BLK 16   // 2048 / 128
#define SCAN_TPB 512
#define KPT 64            // k-elements per thread: 2048 / (512/16)
#define FLAG_STRIDE 8     // 8 u32 = 32B spacing -> distinct L2 sectors

// ---------------- GEMM config ----------------
#define BK 16

// ---------------- scratch (static device globals) ----------
__device__ float g_xw[S_LEN * HID];     // input projection for current layer
__device__ float g_buf0[S_LEN * HID];   // layer output ping
__device__ float g_buf1[S_LEN * HID];   // layer output pong
__device__ float g_h[2][HID];           // hidden-state ping-pong
__device__ unsigned g_flags[GBLK * FLAG_STRIDE];  // per-block step counters

// ---------------- f32x2 helpers (proven R4/R5) ----------------
__device__ __forceinline__ void fma2(unsigned long long& d, unsigned long long a,
                                     unsigned long long b, unsigned long long c) {
    asm("fma.rn.f32x2 %0, %1, %2, %3;" : "=l"(d) : "l"(a), "l"(b), "l"(c));
}
__device__ __forceinline__ unsigned long long pack2(float lo, float hi) {
    unsigned long long r;
    asm("mov.b64 %0, {%1, %2};" : "=l"(r) : "f"(lo), "f"(hi));
    return r;
}
__device__ __forceinline__ float2 unpack2(unsigned long long v) {
    float2 f;
    asm("mov.b64 {%0, %1}, %2;" : "=f"(f.x), "=f"(f.y) : "l"(v));
    return f;
}

// ---------------------------------------------------------------------------
// reset: zero hidden-state ping-pong and all per-block flags
// ---------------------------------------------------------------------------
__global__ void reset_kernel() {
    int i = threadIdx.x;
    float* h = &g_h[0][0];
    for (int j = i; j < 2 * HID; j += blockDim.x) h[j] = 0.0f;
    for (int j = i; j < GBLK * FLAG_STRIDE; j += blockDim.x) g_flags[j] = 0u;
}

// ---------------------------------------------------------------------------
// GEMM (verbatim from PASSING R4/R5): C[i,j] = sum_k A[i,k]*B[j,k]
// 128x128 tile, BK=16, double-buffered SMEM, 256 threads, 8x8/thread, f32x2.
// ---------------------------------------------------------------------------
__global__ void __launch_bounds__(256, 2) gemm_kernel(const float* __restrict__ A,
                                                      const float* __restrict__ B,
                                                      float* __restrict__ C) {
    const int K = HID;
    const int N = HID;
    __shared__ float As[2][BK][128];
    __shared__ float Bs[2][BK][128];

    const int tid  = threadIdx.x;
    const int tx   = tid & 15;
    const int ty   = tid >> 4;
    const int lrow = tid >> 1;
    const int lk   = (tid & 1) * 8;

    const float* Ap = A + (size_t)(blockIdx.y * 128 + lrow) * K + lk;
    const float* Bp = B + (size_t)(blockIdx.x * 128 + lrow) * K + lk;

    unsigned long long acc2[8][4];
    const unsigned long long z2 = pack2(0.0f, 0.0f);
#pragma unroll
    for (int i = 0; i < 8; i++)
#pragma unroll
        for (int j = 0; j < 4; j++) acc2[i][j] = z2;

    {
        float4 a0 = *(const float4*)(Ap);
        float4 a1 = *(const float4*)(Ap + 4);
        float4 b0 = *(const float4*)(Bp);
        float4 b1 = *(const float4*)(Bp + 4);
        As[0][lk + 0][lrow] = a0.x; As[0][lk + 1][lrow] = a0.y;
        As[0][lk + 2][lrow] = a0.z; As[0][lk + 3][lrow] = a0.w;
        As[0][lk + 4][lrow] = a1.x; As[0][lk + 5][lrow] = a1.y;
        As[0][lk + 6][lrow] = a1.z; As[0][lk + 7][lrow] = a1.w;
        Bs[0][lk + 0][lrow] = b0.x; Bs[0][lk + 1][lrow] = b0.y;
        Bs[0][lk + 2][lrow] = b0.z; Bs[0][lk + 3][lrow] = b0.w;
        Bs[0][lk + 4][lrow] = b1.x; Bs[0][lk + 5][lrow] = b1.y;
        Bs[0][lk + 6][lrow] = b1.z; Bs[0][lk + 7][lrow] = b1.w;
    }
    __syncthreads();

    int cur = 0;
    for (int k0 = BK; k0 <= K; k0 += BK) {
        float4 na0, na1, nb0, nb1;
        const bool more = (k0 < K);
        if (more) {
            na0 = *(const float4*)(Ap + k0);
            na1 = *(const float4*)(Ap + k0 + 4);
            nb0 = *(const float4*)(Bp + k0);
            nb1 = *(const float4*)(Bp + k0 + 4);
        }

#pragma unroll
        for (int kk = 0; kk < BK; kk++) {
            float4 a0 = *(const float4*)&As[cur][kk][ty * 8];
            float4 a1 = *(const float4*)&As[cur][kk][ty * 8 + 4];
            ulonglong2 bp0 = *(const ulonglong2*)&Bs[cur][kk][tx * 8];
            ulonglong2 bp1 = *(const ulonglong2*)&Bs[cur][kk][tx * 8 + 4];
            float a[8] = {a0.x, a0.y, a0.z, a0.w, a1.x, a1.y, a1.z, a1.w};
#pragma unroll
            for (int i = 0; i < 8; i++) {
                unsigned long long aa = pack2(a[i], a[i]);
                fma2(acc2[i][0], aa, bp0.x, acc2[i][0]);
                fma2(acc2[i][1], aa, bp0.y, acc2[i][1]);
                fma2(acc2[i][2], aa, bp1.x, acc2[i][2]);
                fma2(acc2[i][3], aa, bp1.y, acc2[i][3]);
            }
        }

        if (more) {
            int nxt = cur ^ 1;
            As[nxt][lk + 0][lrow] = na0.x; As[nxt][lk + 1][lrow] = na0.y;
            As[nxt][lk + 2][lrow] = na0.z; As[nxt][lk + 3][lrow] = na0.w;
            As[nxt][lk + 4][lrow] = na1.x; As[nxt][lk + 5][lrow] = na1.y;
            As[nxt][lk + 6][lrow] = na1.z; As[nxt][lk + 7][lrow] = na1.w;
            Bs[nxt][lk + 0][lrow] = nb0.x; Bs[nxt][lk + 1][lrow] = nb0.y;
            Bs[nxt][lk + 2][lrow] = nb0.z; Bs[nxt][lk + 3][lrow] = nb0.w;
            Bs[nxt][lk + 4][lrow] = nb1.x; Bs[nxt][lk + 5][lrow] = nb1.y;
            Bs[nxt][lk + 6][lrow] = nb1.z; Bs[nxt][lk + 7][lrow] = nb1.w;
            __syncthreads();
            cur = nxt;
        }
    }

#pragma unroll
    for (int i = 0; i < 8; i++) {
        float* Cp = C + (size_t)(blockIdx.y * 128 + ty * 8 + i) * N +
                    blockIdx.x * 128 + tx * 8;
        float2 c0 = unpack2(acc2[i][0]);
        float2 c1 = unpack2(acc2[i][1]);
        float2 c2 = unpack2(acc2[i][2]);
        float2 c3 = unpack2(acc2[i][3]);
        *(float4*)(Cp + 0) = make_float4(c0.x, c0.y, c1.x, c1.y);
        *(float4*)(Cp + 4) = make_float4(c2.x, c2.y, c3.x, c3.y);
    }
}

// ---------------------------------------------------------------------------
// Persistent recurrence: h_t = relu(xw_t + W_hh @ h_{t-1})
// Distributed-flag sync (monotonic per-block step counters):
//   producer b finishing step t: [16 h-stores] -> __syncwarp -> tid0
//     st.release.gpu g_flags[b] = t+1
//   consumer thread tid at step t waits ONLY on flag of block tid>>2
//     (owner of its 4-float h chunk): each poll = ld.acquire flag THEN
//     ld.cg.v4 h; when the acquire passes, that iteration's h is valid.
// No central counter, no full-grid convergence, one L2 round trip on the
// critical path. Depth-2 buffer safe: a producer entering step t+1 polls
// our flag >= t+1, which we publish only after our step-t reads finished.
// ---------------------------------------------------------------------------
__global__ void __launch_bounds__(SCAN_TPB, 1) scan_kernel(
    const float* __restrict__ xw, const float* __restrict__ whh,
    float* __restrict__ y, float* __restrict__ hlast) {
    __shared__ float hbuf[HID];
    __shared__ float part[16][ROWS_PER_BLK];

    const int tid  = threadIdx.x;
    const int row  = tid & 15;
    const int kg   = tid >> 4;
    const int k0   = kg * KPT;
    const int rowG = blockIdx.x * ROWS_PER_BLK + row;
    const int warp = tid >> 5;
    const int lane = tid & 31;
    const int col  = blockIdx.x * ROWS_PER_BLK + tid;    // used when tid<16
    const unsigned* myflag = &g_flags[(tid >> 2) * FLAG_STRIDE];  // producer of my chunk
    unsigned* ourflag = &g_flags[blockIdx.x * FLAG_STRIDE];

    // W_hh slice -> registers as f32x2 pairs
    unsigned long long wp[KPT / 2];
    {
        const float* wr = whh + (size_t)rowG * HID + k0;
#pragma unroll
        for (int i = 0; i < KPT / 4; i++) {
            ulonglong2 v = *(const ulonglong2*)(wr + i * 4);
            wp[2 * i]     = v.x;
            wp[2 * i + 1] = v.y;
        }
    }

    int p = 0;
    for (int t = 0; t < S_LEN; ++t) {
        // prefetch xw early (immutable within the layer)
        float xwv = 0.0f;
        if (tid < ROWS_PER_BLK) xwv = __ldg(&xw[(size_t)t * HID + col]);

        // fused wait+load: poll producer's flag, load h chunk each iteration;
        // on the passing iteration the h load is ordered after the acquire.
        {
            const float* hp = &g_h[p][tid * 4];
            unsigned v;
            float h0, h1, h2, h3;
            do {
                asm volatile("ld.acquire.gpu.global.u32 %0, [%1];"
                             : "=r"(v) : "l"(myflag) : "memory");
                asm volatile("ld.global.cg.v4.f32 {%0,%1,%2,%3}, [%4];"
                             : "=f"(h0), "=f"(h1), "=f"(h2), "=f"(h3)
                             : "l"(hp) : "memory");
            } while ((int)v < t);
            *(float4*)&hbuf[tid * 4] = make_float4(h0, h1, h2, h3);
        }
        __syncthreads();

        // dot product: 32 packed FFMA2 from register-resident W
        unsigned long long a0, a1, a2, a3;
        a0 = a1 = a2 = a3 = pack2(0.0f, 0.0f);
#pragma unroll
        for (int i = 0; i < KPT / 8; i++) {
            ulonglong2 h0 = *(const ulonglong2*)&hbuf[k0 + i * 8];
            ulonglong2 h1 = *(const ulonglong2*)&hbuf[k0 + i * 8 + 4];
            fma2(a0, wp[4 * i + 0], h0.x, a0);
            fma2(a1, wp[4 * i + 1], h0.y, a1);
            fma2(a2, wp[4 * i + 2], h1.x, a2);
            fma2(a3, wp[4 * i + 3], h1.y, a3);
        }
        float2 f0 = unpack2(a0), f1 = unpack2(a1);
        float2 f2 = unpack2(a2), f3 = unpack2(a3);
        float acc = ((f0.x + f0.y) + (f1.x + f1.y)) +
                    ((f2.x + f2.y) + (f3.x + f3.y));

        // combine the two k-groups living in one warp
        acc += __shfl_down_sync(0xffffffffu, acc, 16);
        if (lane < 16) part[warp][lane] = acc;
        __syncthreads();

        // final reduce + relu + publish + flag release (warp 0, lanes 0-15)
        if (tid < ROWS_PER_BLK) {
            float s = 0.f;
#pragma unroll
            for (int q = 0; q < 16; q++) s += part[q][tid];
            float hv = fmaxf(s + xwv, 0.0f);
            g_h[p ^ 1][col]          = hv;
            y[(size_t)t * HID + col] = hv;
            if (hlast != nullptr && t == S_LEN - 1) hlast[col] = hv;
            __syncwarp(0x0000ffffu);   // all 16 h-stores done before release
            if (tid == 0) {
                asm volatile("st.release.gpu.global.u32 [%0], %1;"
                             :: "l"(ourflag), "r"((unsigned)(t + 1)) : "memory");
            }
        }
        p ^= 1;
        // no trailing bar: next iteration's hbuf writes are gated by each
        // thread's own poll; all hbuf reads for step t finished before the
        // part[] __syncthreads; part[] rewrite at t+1 is gated by the
        // post-poll __syncthreads which tid<16 reach only after publishing.
    }
}

// ---------------------------------------------------------------------------
// host launcher (graph-capturable: kernel launches only)
// ---------------------------------------------------------------------------
extern "C" void kernel_launch(void* const* d_in, const int* in_sizes, int n_in,
                              void* d_out, int out_size) {
    const float* x0  = (const float*)d_in[0];
    const float* wih = (const float*)d_in[1];
    const float* whh = (const float*)d_in[2];
    float* out = (float*)d_out;

    void *p_xw, *p_b0, *p_b1;
    cudaGetSymbolAddress(&p_xw, g_xw);
    cudaGetSymbolAddress(&p_b0, g_buf0);
    cudaGetSymbolAddress(&p_b1, g_buf1);
    float* bufs[2] = {(float*)p_b0, (float*)p_b1};

    float* hlast = (out_size >= S_LEN * HID + HID) ? out + (size_t)S_LEN * HID
                                                   : nullptr;

    const float* x = x0;
    dim3 ggrid(HID / 128, S_LEN / 128);
    for (int L = 0; L < NLAYERS; ++L) {
        reset_kernel<<<1, 512>>>();
        gemm_kernel<<<ggrid, 256>>>(x, wih + (size_t)L * HID * HID, (float*)p_xw);
        float* yout = (L == NLAYERS - 1) ? out : bufs[L & 1];
        scan_kernel<<<GBLK, SCAN_TPB>>>((const float*)p_xw,
                                        whh + (size_t)L * HID * HID, yout,
                                        (L == NLAYERS - 1) ? hlast : nullptr);
        x = yout;
    }
}

// round 9
// speedup vs baseline: 1.5742x; 1.5742x over previous
#include <cuda_runtime.h>

#define S_LEN 4096
#define HID 2048
#define NLAYERS 4

// ---------------- scan (recurrence) config ----------------
#define GBLK 128          // persistent blocks; all co-resident (proven)
#define ROWS_PER_BLK 16   // 2048 / 128
#define SCAN_TPB 512
#define KPT 64            // k-elements per thread: 2048 / (512/16)

// ---------------- GEMM config ----------------
#define BK 16

// ---------------- scratch (static device globals) ----------
__device__ float g_xw[S_LEN * HID];     // input projection for current layer
__device__ float g_buf0[S_LEN * HID];   // layer output ping
__device__ float g_buf1[S_LEN * HID];   // layer output pong
__device__ float g_h[2][HID];           // hidden-state ping-pong
__device__ unsigned int g_bar;          // grid barrier counter

// ---------------- f32x2 helpers (proven R4/R5) ----------------
__device__ __forceinline__ void fma2(unsigned long long& d, unsigned long long a,
                                     unsigned long long b, unsigned long long c) {
    asm("fma.rn.f32x2 %0, %1, %2, %3;" : "=l"(d) : "l"(a), "l"(b), "l"(c));
}
__device__ __forceinline__ unsigned long long pack2(float lo, float hi) {
    unsigned long long r;
    asm("mov.b64 %0, {%1, %2};" : "=l"(r) : "f"(lo), "f"(hi));
    return r;
}
__device__ __forceinline__ float2 unpack2(unsigned long long v) {
    float2 f;
    asm("mov.b64 {%0, %1}, %2;" : "=f"(f.x), "=f"(f.y) : "l"(v));
    return f;
}

// ---------------------------------------------------------------------------
// reset (verbatim from passing R5): zero barrier counter + hidden state
// ---------------------------------------------------------------------------
__global__ void reset_kernel() {
    int i = threadIdx.x;
    if (i == 0) g_bar = 0u;
    float* h = &g_h[0][0];
    for (int j = i; j < 2 * HID; j += blockDim.x) h[j] = 0.0f;
}

// ---------------------------------------------------------------------------
// GEMM (verbatim from PASSING R4/R5): C[i,j] = sum_k A[i,k]*B[j,k]
// 128x128 tile, BK=16, double-buffered SMEM, 256 threads, 8x8/thread, f32x2.
// ---------------------------------------------------------------------------
__global__ void __launch_bounds__(256, 2) gemm_kernel(const float* __restrict__ A,
                                                      const float* __restrict__ B,
                                                      float* __restrict__ C) {
    const int K = HID;
    const int N = HID;
    __shared__ float As[2][BK][128];
    __shared__ float Bs[2][BK][128];

    const int tid  = threadIdx.x;
    const int tx   = tid & 15;
    const int ty   = tid >> 4;
    const int lrow = tid >> 1;
    const int lk   = (tid & 1) * 8;

    const float* Ap = A + (size_t)(blockIdx.y * 128 + lrow) * K + lk;
    const float* Bp = B + (size_t)(blockIdx.x * 128 + lrow) * K + lk;

    unsigned long long acc2[8][4];
    const unsigned long long z2 = pack2(0.0f, 0.0f);
#pragma unroll
    for (int i = 0; i < 8; i++)
#pragma unroll
        for (int j = 0; j < 4; j++) acc2[i][j] = z2;

    {
        float4 a0 = *(const float4*)(Ap);
        float4 a1 = *(const float4*)(Ap + 4);
        float4 b0 = *(const float4*)(Bp);
        float4 b1 = *(const float4*)(Bp + 4);
        As[0][lk + 0][lrow] = a0.x; As[0][lk + 1][lrow] = a0.y;
        As[0][lk + 2][lrow] = a0.z; As[0][lk + 3][lrow] = a0.w;
        As[0][lk + 4][lrow] = a1.x; As[0][lk + 5][lrow] = a1.y;
        As[0][lk + 6][lrow] = a1.z; As[0][lk + 7][lrow] = a1.w;
        Bs[0][lk + 0][lrow] = b0.x; Bs[0][lk + 1][lrow] = b0.y;
        Bs[0][lk + 2][lrow] = b0.z; Bs[0][lk + 3][lrow] = b0.w;
        Bs[0][lk + 4][lrow] = b1.x; Bs[0][lk + 5][lrow] = b1.y;
        Bs[0][lk + 6][lrow] = b1.z; Bs[0][lk + 7][lrow] = b1.w;
    }
    __syncthreads();

    int cur = 0;
    for (int k0 = BK; k0 <= K; k0 += BK) {
        float4 na0, na1, nb0, nb1;
        const bool more = (k0 < K);
        if (more) {
            na0 = *(const float4*)(Ap + k0);
            na1 = *(const float4*)(Ap + k0 + 4);
            nb0 = *(const float4*)(Bp + k0);
            nb1 = *(const float4*)(Bp + k0 + 4);
        }

#pragma unroll
        for (int kk = 0; kk < BK; kk++) {
            float4 a0 = *(const float4*)&As[cur][kk][ty * 8];
            float4 a1 = *(const float4*)&As[cur][kk][ty * 8 + 4];
            ulonglong2 bp0 = *(const ulonglong2*)&Bs[cur][kk][tx * 8];
            ulonglong2 bp1 = *(const ulonglong2*)&Bs[cur][kk][tx * 8 + 4];
            float a[8] = {a0.x, a0.y, a0.z, a0.w, a1.x, a1.y, a1.z, a1.w};
#pragma unroll
            for (int i = 0; i < 8; i++) {
                unsigned long long aa = pack2(a[i], a[i]);
                fma2(acc2[i][0], aa, bp0.x, acc2[i][0]);
                fma2(acc2[i][1], aa, bp0.y, acc2[i][1]);
                fma2(acc2[i][2], aa, bp1.x, acc2[i][2]);
                fma2(acc2[i][3], aa, bp1.y, acc2[i][3]);
            }
        }

        if (more) {
            int nxt = cur ^ 1;
            As[nxt][lk + 0][lrow] = na0.x; As[nxt][lk + 1][lrow] = na0.y;
            As[nxt][lk + 2][lrow] = na0.z; As[nxt][lk + 3][lrow] = na0.w;
            As[nxt][lk + 4][lrow] = na1.x; As[nxt][lk + 5][lrow] = na1.y;
            As[nxt][lk + 6][lrow] = na1.z; As[nxt][lk + 7][lrow] = na1.w;
            Bs[nxt][lk + 0][lrow] = nb0.x; Bs[nxt][lk + 1][lrow] = nb0.y;
            Bs[nxt][lk + 2][lrow] = nb0.z; Bs[nxt][lk + 3][lrow] = nb0.w;
            Bs[nxt][lk + 4][lrow] = nb1.x; Bs[nxt][lk + 5][lrow] = nb1.y;
            Bs[nxt][lk + 6][lrow] = nb1.z; Bs[nxt][lk + 7][lrow] = nb1.w;
            __syncthreads();
            cur = nxt;
        }
    }

#pragma unroll
    for (int i = 0; i < 8; i++) {
        float* Cp = C + (size_t)(blockIdx.y * 128 + ty * 8 + i) * N +
                    blockIdx.x * 128 + tx * 8;
        float2 c0 = unpack2(acc2[i][0]);
        float2 c1 = unpack2(acc2[i][1]);
        float2 c2 = unpack2(acc2[i][2]);
        float2 c3 = unpack2(acc2[i][3]);
        *(float4*)(Cp + 0) = make_float4(c0.x, c0.y, c1.x, c1.y);
        *(float4*)(Cp + 4) = make_float4(c2.x, c2.y, c3.x, c3.y);
    }
}

// ---------------------------------------------------------------------------
// Persistent recurrence: h_t = relu(xw_t + W_hh @ h_{t-1})
// Sync protocol IDENTICAL to PASSING R5: central counter, tid0 arrival via
// red.release.gpu, tid0 poll via ld.acquire.gpu, bar relays to block.
// Protocol-neutral trims vs R5:
//   - bar before release -> __syncwarp(0xffff) (publishers all in warp 0)
//   - y/hlast stores moved after the release (outputs, not protocol state)
//   - tree reduce of the 16 partials
// ---------------------------------------------------------------------------
__global__ void __launch_bounds__(SCAN_TPB, 1) scan_kernel(
    const float* __restrict__ xw, const float* __restrict__ whh,
    float* __restrict__ y, float* __restrict__ hlast) {
    __shared__ float hbuf[HID];
    __shared__ float part[16][ROWS_PER_BLK];

    const int tid  = threadIdx.x;
    const int row  = tid & 15;
    const int kg   = tid >> 4;
    const int k0   = kg * KPT;
    const int rowG = blockIdx.x * ROWS_PER_BLK + row;
    const int warp = tid >> 5;
    const int lane = tid & 31;
    const int col  = blockIdx.x * ROWS_PER_BLK + tid;  // used when tid<16

    // W_hh slice -> registers as f32x2 pairs
    unsigned long long wp[KPT / 2];
    {
        const float* wr = whh + (size_t)rowG * HID + k0;
#pragma unroll
        for (int i = 0; i < KPT / 4; i++) {
            ulonglong2 v = *(const ulonglong2*)(wr + i * 4);
            wp[2 * i]     = v.x;
            wp[2 * i + 1] = v.y;
        }
    }

    int p = 0;
    for (int t = 0; t < S_LEN; ++t) {
        // prefetch xw early (immutable within the layer)
        float xwv = 0.0f;
        if (tid < ROWS_PER_BLK) xwv = __ldg(&xw[(size_t)t * HID + col]);

        // broadcast h_{t-1}: one float4 per thread, L2 load
        float4 hv4 = __ldcg((const float4*)&g_h[p][tid * 4]);
        *(float4*)&hbuf[tid * 4] = hv4;
        __syncthreads();

        // dot product: 32 packed FFMA2 from register-resident W
        unsigned long long a0, a1, a2, a3;
        a0 = a1 = a2 = a3 = pack2(0.0f, 0.0f);
#pragma unroll
        for (int i = 0; i < KPT / 8; i++) {
            ulonglong2 h0 = *(const ulonglong2*)&hbuf[k0 + i * 8];
            ulonglong2 h1 = *(const ulonglong2*)&hbuf[k0 + i * 8 + 4];
            fma2(a0, wp[4 * i + 0], h0.x, a0);
            fma2(a1, wp[4 * i + 1], h0.y, a1);
            fma2(a2, wp[4 * i + 2], h1.x, a2);
            fma2(a3, wp[4 * i + 3], h1.y, a3);
        }
        float2 f0 = unpack2(a0), f1 = unpack2(a1);
        float2 f2 = unpack2(a2), f3 = unpack2(a3);
        float acc = ((f0.x + f0.y) + (f1.x + f1.y)) +
                    ((f2.x + f2.y) + (f3.x + f3.y));

        // combine the two k-groups living in one warp
        acc += __shfl_down_sync(0xffffffffu, acc, 16);
        if (lane < 16) part[warp][lane] = acc;
        __syncthreads();

        // final reduce (tree) + relu + publish h + release; y-store off path
        if (tid < ROWS_PER_BLK) {
            float s01 = part[0][tid]  + part[1][tid];
            float s23 = part[2][tid]  + part[3][tid];
            float s45 = part[4][tid]  + part[5][tid];
            float s67 = part[6][tid]  + part[7][tid];
            float s89 = part[8][tid]  + part[9][tid];
            float sab = part[10][tid] + part[11][tid];
            float scd = part[12][tid] + part[13][tid];
            float sef = part[14][tid] + part[15][tid];
            float s = ((s01 + s23) + (s45 + s67)) + ((s89 + sab) + (scd + sef));
            float hv = fmaxf(s + xwv, 0.0f);
            g_h[p ^ 1][col] = hv;              // protocol state: before release
            __syncwarp(0x0000ffffu);           // order 16 h-stores in warp 0
            if (tid == 0) {
                asm volatile("red.release.gpu.global.add.u32 [%0], %1;"
                             :: "l"(&g_bar), "r"(1u) : "memory");
            }
            // outputs (read only across kernel boundary): off critical path
            y[(size_t)t * HID + col] = hv;
            if (hlast != nullptr && t == S_LEN - 1) hlast[col] = hv;
        }

        // tid0 polls the counter; bar relays release+visibility to the block
        if (tid == 0) {
            const unsigned target = (unsigned)(t + 1) * (unsigned)GBLK;
            unsigned v;
            do {
                asm volatile("ld.acquire.gpu.global.u32 %0, [%1];"
                             : "=r"(v) : "l"(&g_bar) : "memory");
            } while (v < target);
        }
        __syncthreads();
        p ^= 1;
    }
}

// ---------------------------------------------------------------------------
// host launcher (graph-capturable: kernel launches only)
// ---------------------------------------------------------------------------
extern "C" void kernel_launch(void* const* d_in, const int* in_sizes, int n_in,
                              void* d_out, int out_size) {
    const float* x0  = (const float*)d_in[0];
    const float* wih = (const float*)d_in[1];
    const float* whh = (const float*)d_in[2];
    float* out = (float*)d_out;

    void *p_xw, *p_b0, *p_b1;
    cudaGetSymbolAddress(&p_xw, g_xw);
    cudaGetSymbolAddress(&p_b0, g_buf0);
    cudaGetSymbolAddress(&p_b1, g_buf1);
    float* bufs[2] = {(float*)p_b0, (float*)p_b1};

    float* hlast = (out_size >= S_LEN * HID + HID) ? out + (size_t)S_LEN * HID
                                                   : nullptr;

    const float* x = x0;
    dim3 ggrid(HID / 128, S_LEN / 128);
    for (int L = 0; L < NLAYERS; ++L) {
        reset_kernel<<<1, 512>>>();
        gemm_kernel<<<ggrid, 256>>>(x, wih + (size_t)L * HID * HID, (float*)p_xw);
        float* yout = (L == NLAYERS - 1) ? out : bufs[L & 1];
        scan_kernel<<<GBLK, SCAN_TPB>>>((const float*)p_xw,
                                        whh + (size_t)L * HID * HID, yout,
                                        (L == NLAYERS - 1) ? hlast : nullptr);
        x = yout;
    }
}